// round 10
// baseline (speedup 1.0000x reference)
#include <cuda_runtime.h>
#include <cstdint>

typedef unsigned long long ull;
typedef unsigned int uint;

#define NT 256

// ---------------- dynamic smem layout (bytes) ----------------
#define OFF_PX   0
#define OFF_PY   512
#define OFF_PZ   1024
#define OFF_SQ   1536
#define OFF_W1   2048     // 3*32*4 = 384
#define OFF_B1   2432     // 128
#define OFF_B2   2560     // 256
#define OFF_B3   2816     // 512
#define OFF_W2Q  3328     // float4[8][2][32]  = 8192
#define OFF_W3Q  11520    // float4[16][4][32] = 32768
#define OFF_RELX 44288    // 128*16*4 = 8192
#define OFF_RELY 52480
#define OFF_RELZ 60672
#define SMEM_TOTAL 68864

__device__ __forceinline__ uint tf32u(float x) {
    uint r;
    asm("cvt.rna.tf32.f32 %0, %1;" : "=r"(r) : "f"(x));
    return r;
}
__device__ __forceinline__ float tf32f(float x) { return __uint_as_float(tf32u(x)); }

__device__ __forceinline__ void mma8(float c[4], const uint a[4], float b0f, float b1f) {
    uint b0 = __float_as_uint(b0f), b1 = __float_as_uint(b1f);
    asm volatile(
        "mma.sync.aligned.m16n8k8.row.col.f32.tf32.tf32.f32 "
        "{%0,%1,%2,%3}, {%4,%5,%6,%7}, {%8,%9}, {%0,%1,%2,%3};"
        : "+f"(c[0]), "+f"(c[1]), "+f"(c[2]), "+f"(c[3])
        : "r"(a[0]), "r"(a[1]), "r"(a[2]), "r"(a[3]), "r"(b0), "r"(b1));
}

// hidden-basis permutation within each 8-col block (see R9 derivation):
// original col at stored position q:  pinv(q) = (q&1) ? (q>>1)+4 : (q>>1)
__device__ __host__ __forceinline__ int pinv(int q) {
    return (q & 1) ? ((q >> 1) + 4) : (q >> 1);
}

__device__ __forceinline__ uint fmono(float x) {
    uint b = __float_as_uint(x);
    return b ^ (uint)((((int)b) >> 31) | 0x80000000);
}
__device__ __forceinline__ void cas(uint& a, uint& b) {
    uint lo = umin(a, b), hi = umax(a, b);
    a = lo; b = hi;
}
__device__ __forceinline__ void sort8(uint k[8]) {
    cas(k[0],k[1]); cas(k[2],k[3]); cas(k[4],k[5]); cas(k[6],k[7]);
    cas(k[0],k[2]); cas(k[1],k[3]); cas(k[4],k[6]); cas(k[5],k[7]);
    cas(k[1],k[2]); cas(k[5],k[6]); cas(k[0],k[4]); cas(k[1],k[5]);
    cas(k[2],k[6]); cas(k[3],k[7]);
    cas(k[1],k[4]); cas(k[3],k[6]);
    cas(k[2],k[4]); cas(k[3],k[5]);
    cas(k[3],k[4]);
}
__device__ __forceinline__ void pop_shift(uint k[8], uint kmin) {
    if (k[0] == kmin) {
        k[0]=k[1]; k[1]=k[2]; k[2]=k[3]; k[3]=k[4];
        k[4]=k[5]; k[5]=k[6]; k[6]=k[7]; k[7]=0xFFFFFFFFu;
    }
}

__global__ void __launch_bounds__(NT, 2)
mini_embedding_mma(const float* __restrict__ windows,
                   const float* __restrict__ W1, const float* __restrict__ b1,
                   const float* __restrict__ W2, const float* __restrict__ b2,
                   const float* __restrict__ W3, const float* __restrict__ b3,
                   float* __restrict__ out)
{
    extern __shared__ unsigned char smraw[];
    float* px  = (float*)(smraw + OFF_PX);
    float* py  = (float*)(smraw + OFF_PY);
    float* pz  = (float*)(smraw + OFF_PZ);
    float* sqn = (float*)(smraw + OFF_SQ);
    float* sW1 = (float*)(smraw + OFF_W1);
    float* sb1 = (float*)(smraw + OFF_B1);
    float* sb2 = (float*)(smraw + OFF_B2);   // permuted by pi
    float* sb3 = (float*)(smraw + OFF_B3);
    float4* w2Q = (float4*)(smraw + OFF_W2Q);  // [(nt*2+ktp)*32 + lane], output cols permuted
    float4* w3Q = (float4*)(smraw + OFF_W3Q);  // [(ntg*4+ktp)*32 + lane], unpermuted rows
    float* relx = (float*)(smraw + OFF_RELX);
    float* rely = (float*)(smraw + OFF_RELY);
    float* relz = (float*)(smraw + OFF_RELZ);

    const int tid  = threadIdx.x;
    const int w    = tid >> 5;
    const int lane = tid & 31;
    const int g    = lane >> 2;
    const int tg   = lane & 3;
    const int m    = blockIdx.x;

    const bool g0 = (lane >> 2) & 1;
    const bool g1 = (lane >> 3) & 1;
    const int  g2 = (lane >> 4) & 1;

    // ---- cooperative prep ----
    const float* wptr = windows + (size_t)m * 128 * 3;
    for (int i = tid; i < 128; i += NT) {
        float x = wptr[i*3+0], y = wptr[i*3+1], z = wptr[i*3+2];
        px[i] = x; py[i] = y; pz[i] = z;
        sqn[i] = x*x + y*y + z*z;
    }
    for (int i = tid; i < 96;  i += NT) sW1[i] = W1[i];
    for (int i = tid; i < 32;  i += NT) sb1[i] = b1[i];
    for (int i = tid; i < 64;  i += NT) sb2[i] = b2[(i & ~7) | pinv(i & 7)];
    for (int i = tid; i < 128; i += NT) sb3[i] = b3[i];
    // w2Q: packed k-pairs; output col position gg holds original col pinv(gg)
    for (int i = tid; i < 512; i += NT) {
        int ln = i & 31, ktp = (i >> 5) & 1, nt = i >> 6;
        int gg = ln >> 2, tt = ln & 3;
        int c = nt*8 + pinv(gg);
        int ka = 2*ktp*8, kb = (2*ktp+1)*8;
        w2Q[i] = make_float4(tf32f(W2[(ka+tt)*64 + c]),
                             tf32f(W2[(ka+tt+4)*64 + c]),
                             tf32f(W2[(kb+tt)*64 + c]),
                             tf32f(W2[(kb+tt+4)*64 + c]));
    }
    // w3Q: packed k-pairs; rows unpermuted
    for (int i = tid; i < 2048; i += NT) {
        int ln = i & 31, ktp = (i >> 5) & 3, ntg = i >> 7;
        int gg = ln >> 2, tt = ln & 3;
        int n = ntg*8 + gg;
        int ka = 2*ktp*8, kb = (2*ktp+1)*8;
        w3Q[i] = make_float4(tf32f(W3[(ka+tt)*128 + n]),
                             tf32f(W3[(ka+tt+4)*128 + n]),
                             tf32f(W3[(kb+tt)*128 + n]),
                             tf32f(W3[(kb+tt+4)*128 + n]));
    }
    __syncthreads();

    const int half = lane >> 4;
    const int n16  = lane & 15;
    const int jb   = n16 * 8;

    // ---- interleaved: per i4-group, kNN for 4 points then 2 GEMM chunks ----
    #pragma unroll 1
    for (int i4 = 0; i4 < 4; ++i4) {
        // ===== kNN + normalize for points 16w+4i4 .. +3 (lane pair handles 2) =====
        {
            const int q0 = 16*w + 4*i4 + 2*half;
            const int q1 = q0 + 1;
            const float qx0 = px[q0], qy0 = py[q0], qz0 = pz[q0], sq0 = sqn[q0];
            const float qx1 = px[q1], qy1 = py[q1], qz1 = pz[q1], sq1 = sqn[q1];
            uint k0[8], k1[8];
            #pragma unroll
            for (int ii = 0; ii < 8; ++ii) {
                const int j = jb + ii;
                const float xj = px[j], yj = py[j], zj = pz[j], sj = sqn[j];
                float d0 = sq0 + sj - 2.0f*(qx0*xj + qy0*yj + qz0*zj);
                float d1 = sq1 + sj - 2.0f*(qx1*xj + qy1*yj + qz1*zj);
                k0[ii] = (fmono(d0) & 0xFFFFFF80u) | (uint)j;
                k1[ii] = (fmono(d1) & 0xFFFFFF80u) | (uint)j;
            }
            sort8(k0); sort8(k1);
            int idx0 = 0, idx1 = 0;
            #pragma unroll
            for (int r = 0; r < 16; ++r) {
                uint m0 = k0[0], m1 = k1[0];
                #pragma unroll
                for (int st = 1; st < 16; st <<= 1) {
                    m0 = umin(m0, __shfl_xor_sync(0xffffffffu, m0, st, 16));
                    m1 = umin(m1, __shfl_xor_sync(0xffffffffu, m1, st, 16));
                }
                if (r == n16) { idx0 = (int)(m0 & 127u); idx1 = (int)(m1 & 127u); }
                pop_shift(k0, m0);
                pop_shift(k1, m1);
            }
            float rx0 = px[idx0] - qx0, ry0 = py[idx0] - qy0, rz0 = pz[idx0] - qz0;
            float rx1 = px[idx1] - qx1, ry1 = py[idx1] - qy1, rz1 = pz[idx1] - qz1;
            float mx0 = rx0*rx0 + ry0*ry0 + rz0*rz0;
            float mx1 = rx1*rx1 + ry1*ry1 + rz1*rz1;
            #pragma unroll
            for (int st = 1; st < 16; st <<= 1) {
                mx0 = fmaxf(mx0, __shfl_xor_sync(0xffffffffu, mx0, st, 16));
                mx1 = fmaxf(mx1, __shfl_xor_sync(0xffffffffu, mx1, st, 16));
            }
            float inv0 = 1.0f / fmaxf(sqrtf(mx0), 1e-8f);
            float inv1 = 1.0f / fmaxf(sqrtf(mx1), 1e-8f);
            relx[q0*16 + n16] = rx0 * inv0;
            rely[q0*16 + n16] = ry0 * inv0;
            relz[q0*16 + n16] = rz0 * inv0;
            relx[q1*16 + n16] = rx1 * inv1;
            rely[q1*16 + n16] = ry1 * inv1;
            relz[q1*16 + n16] = rz1 * inv1;
        }
        __syncwarp();

        // ===== 2 GEMM chunks for these 4 points =====
        #pragma unroll 1
        for (int cc = 0; cc < 2; ++cc) {
            const int pA = 16*w + 4*i4 + 2*cc;
            const int pB = pA + 1;

            float rX[4], rY[4], rZ[4];
            rX[0] = relx[pA*16+g];   rY[0] = rely[pA*16+g];   rZ[0] = relz[pA*16+g];
            rX[1] = relx[pA*16+g+8]; rY[1] = rely[pA*16+g+8]; rZ[1] = relz[pA*16+g+8];
            rX[2] = relx[pB*16+g];   rY[2] = rely[pB*16+g];   rZ[2] = relz[pB*16+g];
            rX[3] = relx[pB*16+g+8]; rY[3] = rely[pB*16+g+8]; rZ[3] = relz[pB*16+g+8];

            uint afrag[2][4][4];
            #pragma unroll
            for (int j = 0; j < 8; ++j) {
                const int col = tg + 4*j;
                const float w0 = sW1[col], w1 = sW1[32+col], w2 = sW1[64+col], bb = sb1[col];
                const int kt = j >> 1, hi = j & 1;
                #pragma unroll
                for (int mm = 0; mm < 2; ++mm) {
                    float hg  = fmaxf(bb + rX[2*mm+0]*w0 + rY[2*mm+0]*w1 + rZ[2*mm+0]*w2, 0.0f);
                    float hg8 = fmaxf(bb + rX[2*mm+1]*w0 + rY[2*mm+1]*w1 + rZ[2*mm+1]*w2, 0.0f);
                    afrag[mm][kt][hi*2+0] = tf32u(hg);
                    afrag[mm][kt][hi*2+1] = tf32u(hg8);
                }
            }

            // layer 2 (float4 B-frag loads; per-accumulator kt order ascending)
            float c2[2][8][4];
            #pragma unroll
            for (int nt = 0; nt < 8; ++nt)
                #pragma unroll
                for (int r = 0; r < 4; ++r) { c2[0][nt][r] = 0.0f; c2[1][nt][r] = 0.0f; }
            #pragma unroll
            for (int ktp = 0; ktp < 2; ++ktp) {
                #pragma unroll
                for (int nt = 0; nt < 8; ++nt) {
                    float4 bq = w2Q[(nt*2 + ktp)*32 + lane];
                    mma8(c2[0][nt], afrag[0][2*ktp],   bq.x, bq.y);
                    mma8(c2[0][nt], afrag[0][2*ktp+1], bq.z, bq.w);
                    mma8(c2[1][nt], afrag[1][2*ktp],   bq.x, bq.y);
                    mma8(c2[1][nt], afrag[1][2*ktp+1], bq.z, bq.w);
                }
            }

            // epilogue 1: relu(+b2), tf32 round; C-frag IS the A-frag (rename)
            uint af[2][8][4];
            #pragma unroll
            for (int mm = 0; mm < 2; ++mm) {
                #pragma unroll
                for (int nt = 0; nt < 8; ++nt) {
                    const int col = nt*8 + 2*tg;
                    const float b20 = sb2[col], b21 = sb2[col+1];
                    af[mm][nt][0] = tf32u(fmaxf(c2[mm][nt][0] + b20, 0.0f));
                    af[mm][nt][1] = tf32u(fmaxf(c2[mm][nt][2] + b20, 0.0f));
                    af[mm][nt][2] = tf32u(fmaxf(c2[mm][nt][1] + b21, 0.0f));
                    af[mm][nt][3] = tf32u(fmaxf(c2[mm][nt][3] + b21, 0.0f));
                }
            }

            // layer 3 + routed max-reduction epilogue
            const size_t rbA = ((size_t)(m*128 + pA)) * 128;
            const size_t rbB = ((size_t)(m*128 + pB)) * 128;
            #pragma unroll 1
            for (int pp = 0; pp < 2; ++pp) {
                #pragma unroll 1
                for (int nh = 0; nh < 2; ++nh) {
                    float c3[2][4][4];
                    #pragma unroll
                    for (int n2 = 0; n2 < 4; ++n2)
                        #pragma unroll
                        for (int r = 0; r < 4; ++r) { c3[0][n2][r] = 0.0f; c3[1][n2][r] = 0.0f; }
                    #pragma unroll
                    for (int ktp = 0; ktp < 4; ++ktp) {
                        #pragma unroll
                        for (int n2 = 0; n2 < 4; ++n2) {
                            const int ntg = pp*8 + nh*4 + n2;
                            float4 bq = w3Q[(ntg*4 + ktp)*32 + lane];
                            mma8(c3[0][n2], af[0][2*ktp],   bq.x, bq.y);
                            mma8(c3[0][n2], af[0][2*ktp+1], bq.z, bq.w);
                            mma8(c3[1][n2], af[1][2*ktp],   bq.x, bq.y);
                            mma8(c3[1][n2], af[1][2*ktp+1], bq.z, bq.w);
                        }
                    }
                    #pragma unroll
                    for (int mm = 0; mm < 2; ++mm) {
                        float P[4][2];
                        #pragma unroll
                        for (int n2 = 0; n2 < 4; ++n2) {
                            P[n2][0] = fmaxf(c3[mm][n2][0], c3[mm][n2][2]);
                            P[n2][1] = fmaxf(c3[mm][n2][1], c3[mm][n2][3]);
                        }
                        float e0 = g0 ? P[0][0] : P[1][0];
                        float e1 = g0 ? P[0][1] : P[1][1];
                        float e2 = g0 ? P[2][0] : P[3][0];
                        float e3 = g0 ? P[2][1] : P[3][1];
                        float K0v0 = g0 ? P[1][0] : P[0][0];
                        float K0v1 = g0 ? P[1][1] : P[0][1];
                        float K1v0 = g0 ? P[3][0] : P[2][0];
                        float K1v1 = g0 ? P[3][1] : P[2][1];
                        K0v0 = fmaxf(K0v0, __shfl_xor_sync(0xffffffffu, e0, 4));
                        K0v1 = fmaxf(K0v1, __shfl_xor_sync(0xffffffffu, e1, 4));
                        K1v0 = fmaxf(K1v0, __shfl_xor_sync(0xffffffffu, e2, 4));
                        K1v1 = fmaxf(K1v1, __shfl_xor_sync(0xffffffffu, e3, 4));
                        float f0  = g1 ? K0v0 : K1v0;
                        float f1  = g1 ? K0v1 : K1v1;
                        float Rv0 = g1 ? K1v0 : K0v0;
                        float Rv1 = g1 ? K1v1 : K0v1;
                        Rv0 = fmaxf(Rv0, __shfl_xor_sync(0xffffffffu, f0, 8));
                        Rv1 = fmaxf(Rv1, __shfl_xor_sync(0xffffffffu, f1, 8));
                        Rv0 = fmaxf(Rv0, __shfl_xor_sync(0xffffffffu, Rv0, 16));
                        Rv1 = fmaxf(Rv1, __shfl_xor_sync(0xffffffffu, Rv1, 16));
                        if (g2 == nh) {
                            const int col = (pp*8 + nh*4 + (g & 3))*8 + 2*tg;
                            float2 b3v = *(float2*)&sb3[col];
                            *(float2*)&out[(mm ? rbB : rbA) + col] =
                                make_float2(Rv0 + b3v.x, Rv1 + b3v.y);
                        }
                    }
                }
            }
        }
    }
}

extern "C" void kernel_launch(void* const* d_in, const int* in_sizes, int n_in,
                              void* d_out, int out_size)
{
    const float* windows = (const float*)d_in[0];
    const float* W1 = (const float*)d_in[1];
    const float* b1 = (const float*)d_in[2];
    const float* W2 = (const float*)d_in[3];
    const float* b2 = (const float*)d_in[4];
    const float* W3 = (const float*)d_in[5];
    const float* b3 = (const float*)d_in[6];
    float* out = (float*)d_out;

    cudaFuncSetAttribute(mini_embedding_mma,
                         cudaFuncAttributeMaxDynamicSharedMemorySize, SMEM_TOTAL);

    const int M = in_sizes[0] / (128 * 3);
    mini_embedding_mma<<<M, NT, SMEM_TOTAL>>>(windows, W1, b1, W2, b2, W3, b3, out);
}

// round 11
// speedup vs baseline: 2.3352x; 2.3352x over previous
#include <cuda_runtime.h>
#include <cuda_fp16.h>
#include <cstdint>

typedef unsigned int uint;

#define NT 256

// ---------------- dynamic smem layout (bytes) ----------------
#define OFF_PX   0
#define OFF_PY   512
#define OFF_PZ   1024
#define OFF_SQ   1536
#define OFF_W1   2048     // 3*32*4 = 384
#define OFF_B1   2432     // 128
#define OFF_B2   2560     // 256
#define OFF_B3   2816     // 512
#define OFF_W2H  3328     // uint2[8][2][32]  = 4096
#define OFF_W3H  7424     // uint2[16][4][32] = 16384
#define OFF_RELX 23808    // 128*16*4 = 8192
#define OFF_RELY 32000
#define OFF_RELZ 40192
#define SMEM_TOTAL 48384

__device__ __forceinline__ uint packh2(float lo, float hi) {
    __half2 h = __floats2half2_rn(lo, hi);
    return *(uint*)&h;
}

// fp16 mma m16n8k16: D += A*B, fp32 accumulate
__device__ __forceinline__ void mma16(float c[4], const uint a[4], uint b0, uint b1) {
    asm volatile(
        "mma.sync.aligned.m16n8k16.row.col.f32.f16.f16.f32 "
        "{%0,%1,%2,%3}, {%4,%5,%6,%7}, {%8,%9}, {%0,%1,%2,%3};"
        : "+f"(c[0]), "+f"(c[1]), "+f"(c[2]), "+f"(c[3])
        : "r"(a[0]), "r"(a[1]), "r"(a[2]), "r"(a[3]), "r"(b0), "r"(b1));
}

__device__ __forceinline__ uint fmono(float x) {
    uint b = __float_as_uint(x);
    return b ^ (uint)((((int)b) >> 31) | 0x80000000);
}
__device__ __forceinline__ void cas(uint& a, uint& b) {
    uint lo = umin(a, b), hi = umax(a, b);
    a = lo; b = hi;
}
__device__ __forceinline__ void sort8(uint k[8]) {
    cas(k[0],k[1]); cas(k[2],k[3]); cas(k[4],k[5]); cas(k[6],k[7]);
    cas(k[0],k[2]); cas(k[1],k[3]); cas(k[4],k[6]); cas(k[5],k[7]);
    cas(k[1],k[2]); cas(k[5],k[6]); cas(k[0],k[4]); cas(k[1],k[5]);
    cas(k[2],k[6]); cas(k[3],k[7]);
    cas(k[1],k[4]); cas(k[3],k[6]);
    cas(k[2],k[4]); cas(k[3],k[5]);
    cas(k[3],k[4]);
}
__device__ __forceinline__ void pop_shift(uint k[8], uint kmin) {
    if (k[0] == kmin) {
        k[0]=k[1]; k[1]=k[2]; k[2]=k[3]; k[3]=k[4];
        k[4]=k[5]; k[5]=k[6]; k[6]=k[7]; k[7]=0xFFFFFFFFu;
    }
}

__global__ void __launch_bounds__(NT, 2)
mini_embedding_mma(const float* __restrict__ windows,
                   const float* __restrict__ W1, const float* __restrict__ b1,
                   const float* __restrict__ W2, const float* __restrict__ b2,
                   const float* __restrict__ W3, const float* __restrict__ b3,
                   float* __restrict__ out)
{
    extern __shared__ unsigned char smraw[];
    float* px  = (float*)(smraw + OFF_PX);
    float* py  = (float*)(smraw + OFF_PY);
    float* pz  = (float*)(smraw + OFF_PZ);
    float* sqn = (float*)(smraw + OFF_SQ);
    float* sW1 = (float*)(smraw + OFF_W1);
    float* sb1 = (float*)(smraw + OFF_B1);
    float* sb2 = (float*)(smraw + OFF_B2);
    float* sb3 = (float*)(smraw + OFF_B3);
    uint2* w2H = (uint2*)(smraw + OFF_W2H);   // [(nt*2+kt)*32 + lane]
    uint2* w3H = (uint2*)(smraw + OFF_W3H);   // [(ntg*4+kt)*32 + lane]
    float* relx = (float*)(smraw + OFF_RELX);
    float* rely = (float*)(smraw + OFF_RELY);
    float* relz = (float*)(smraw + OFF_RELZ);

    const int tid  = threadIdx.x;
    const int w    = tid >> 5;
    const int lane = tid & 31;
    const int g    = lane >> 2;
    const int tg   = lane & 3;
    const int m    = blockIdx.x;

    const bool g0 = (lane >> 2) & 1;
    const bool g1 = (lane >> 3) & 1;
    const int  g2 = (lane >> 4) & 1;

    // ---- cooperative prep ----
    const float* wptr = windows + (size_t)m * 128 * 3;
    for (int i = tid; i < 128; i += NT) {
        float x = wptr[i*3+0], y = wptr[i*3+1], z = wptr[i*3+2];
        px[i] = x; py[i] = y; pz[i] = z;
        sqn[i] = x*x + y*y + z*z;
    }
    for (int i = tid; i < 96;  i += NT) sW1[i] = W1[i];
    for (int i = tid; i < 32;  i += NT) sb1[i] = b1[i];
    for (int i = tid; i < 64;  i += NT) sb2[i] = b2[i];
    for (int i = tid; i < 128; i += NT) sb3[i] = b3[i];
    // w2H: fp16 B-frags. entry (nt,kt,lane): col c=nt*8+gg;
    //   x = {W2[16kt+2tt][c], W2[16kt+2tt+1][c]}, y = same at k+8
    for (int i = tid; i < 512; i += NT) {
        int ln = i & 31, kt = (i >> 5) & 1, nt = i >> 6;
        int gg = ln >> 2, tt = ln & 3;
        int c = nt*8 + gg;
        int k0 = 16*kt + 2*tt;
        w2H[i] = make_uint2(packh2(W2[k0*64 + c],     W2[(k0+1)*64 + c]),
                            packh2(W2[(k0+8)*64 + c], W2[(k0+9)*64 + c]));
    }
    // w3H: same packing for W3 (16 ntg, 4 kt)
    for (int i = tid; i < 2048; i += NT) {
        int ln = i & 31, kt = (i >> 5) & 3, ntg = i >> 7;
        int gg = ln >> 2, tt = ln & 3;
        int c = ntg*8 + gg;
        int k0 = 16*kt + 2*tt;
        w3H[i] = make_uint2(packh2(W3[k0*128 + c],     W3[(k0+1)*128 + c]),
                            packh2(W3[(k0+8)*128 + c], W3[(k0+9)*128 + c]));
    }
    __syncthreads();

    // ---- warp-local kNN + normalize (unchanged from R9) ----
    const int half = lane >> 4;
    const int n16  = lane & 15;
    const int jb   = n16 * 8;
    #pragma unroll 1
    for (int i4 = 0; i4 < 4; ++i4) {
        const int q0 = 16*w + 4*i4 + 2*half;
        const int q1 = q0 + 1;
        const float qx0 = px[q0], qy0 = py[q0], qz0 = pz[q0], sq0 = sqn[q0];
        const float qx1 = px[q1], qy1 = py[q1], qz1 = pz[q1], sq1 = sqn[q1];
        uint k0[8], k1[8];
        #pragma unroll
        for (int ii = 0; ii < 8; ++ii) {
            const int j = jb + ii;
            const float xj = px[j], yj = py[j], zj = pz[j], sj = sqn[j];
            float d0 = sq0 + sj - 2.0f*(qx0*xj + qy0*yj + qz0*zj);
            float d1 = sq1 + sj - 2.0f*(qx1*xj + qy1*yj + qz1*zj);
            k0[ii] = (fmono(d0) & 0xFFFFFF80u) | (uint)j;
            k1[ii] = (fmono(d1) & 0xFFFFFF80u) | (uint)j;
        }
        sort8(k0); sort8(k1);
        int idx0 = 0, idx1 = 0;
        #pragma unroll
        for (int r = 0; r < 16; ++r) {
            uint m0 = k0[0], m1 = k1[0];
            #pragma unroll
            for (int st = 1; st < 16; st <<= 1) {
                m0 = umin(m0, __shfl_xor_sync(0xffffffffu, m0, st, 16));
                m1 = umin(m1, __shfl_xor_sync(0xffffffffu, m1, st, 16));
            }
            if (r == n16) { idx0 = (int)(m0 & 127u); idx1 = (int)(m1 & 127u); }
            pop_shift(k0, m0);
            pop_shift(k1, m1);
        }
        float rx0 = px[idx0] - qx0, ry0 = py[idx0] - qy0, rz0 = pz[idx0] - qz0;
        float rx1 = px[idx1] - qx1, ry1 = py[idx1] - qy1, rz1 = pz[idx1] - qz1;
        float mx0 = rx0*rx0 + ry0*ry0 + rz0*rz0;
        float mx1 = rx1*rx1 + ry1*ry1 + rz1*rz1;
        #pragma unroll
        for (int st = 1; st < 16; st <<= 1) {
            mx0 = fmaxf(mx0, __shfl_xor_sync(0xffffffffu, mx0, st, 16));
            mx1 = fmaxf(mx1, __shfl_xor_sync(0xffffffffu, mx1, st, 16));
        }
        float inv0 = 1.0f / fmaxf(sqrtf(mx0), 1e-8f);
        float inv1 = 1.0f / fmaxf(sqrtf(mx1), 1e-8f);
        relx[q0*16 + n16] = rx0 * inv0;
        rely[q0*16 + n16] = ry0 * inv0;
        relz[q0*16 + n16] = rz0 * inv0;
        relx[q1*16 + n16] = rx1 * inv1;
        rely[q1*16 + n16] = ry1 * inv1;
        relz[q1*16 + n16] = rz1 * inv1;
    }
    __syncwarp();

    // ---- per-chunk GEMM pipeline: 8 chunks of (2 points x 16 neighbors) ----
    #pragma unroll 1
    for (int ch = 0; ch < 8; ++ch) {
        const int pA = 16*w + 2*ch;
        const int pB = pA + 1;

        float rX[4], rY[4], rZ[4];
        rX[0] = relx[pA*16+g];   rY[0] = rely[pA*16+g];   rZ[0] = relz[pA*16+g];
        rX[1] = relx[pA*16+g+8]; rY[1] = rely[pA*16+g+8]; rZ[1] = relz[pA*16+g+8];
        rX[2] = relx[pB*16+g];   rY[2] = rely[pB*16+g];   rZ[2] = relz[pB*16+g];
        rX[3] = relx[pB*16+g+8]; rY[3] = rely[pB*16+g+8]; rZ[3] = relz[pB*16+g+8];

        // h1 (3->32, relu) packed directly into fp16 A-frags: afrag[mm][kt][4]
        // a0=(row g, k=16kt+2tg,+1) a1=(row g+8, same) a2/a3 = k+8
        uint afrag[2][2][4];
        #pragma unroll
        for (int blk = 0; blk < 4; ++blk) {          // 8-wide k half-blocks
            const int c0 = blk*8 + 2*tg;
            const float wa0 = sW1[c0],    wb0 = sW1[32+c0],    wc0 = sW1[64+c0],    bb0 = sb1[c0];
            const float wa1 = sW1[c0+1],  wb1 = sW1[32+c0+1],  wc1 = sW1[64+c0+1],  bb1 = sb1[c0+1];
            const int kt = blk >> 1, hi = blk & 1;
            #pragma unroll
            for (int mm = 0; mm < 2; ++mm) {
                float hg0  = fmaxf(bb0 + rX[2*mm+0]*wa0 + rY[2*mm+0]*wb0 + rZ[2*mm+0]*wc0, 0.0f);
                float hg1  = fmaxf(bb1 + rX[2*mm+0]*wa1 + rY[2*mm+0]*wb1 + rZ[2*mm+0]*wc1, 0.0f);
                float hg80 = fmaxf(bb0 + rX[2*mm+1]*wa0 + rY[2*mm+1]*wb0 + rZ[2*mm+1]*wc0, 0.0f);
                float hg81 = fmaxf(bb1 + rX[2*mm+1]*wa1 + rY[2*mm+1]*wb1 + rZ[2*mm+1]*wc1, 0.0f);
                afrag[mm][kt][hi*2+0] = packh2(hg0,  hg1);   // row g
                afrag[mm][kt][hi*2+1] = packh2(hg80, hg81);  // row g+8
            }
        }

        // layer 2: C2(32x64) = h1 @ W2, fp16 k16 (2 k-steps)
        float c2[2][8][4];
        #pragma unroll
        for (int nt = 0; nt < 8; ++nt)
            #pragma unroll
            for (int r = 0; r < 4; ++r) { c2[0][nt][r] = 0.0f; c2[1][nt][r] = 0.0f; }
        #pragma unroll
        for (int kt = 0; kt < 2; ++kt) {
            #pragma unroll
            for (int nt = 0; nt < 8; ++nt) {
                uint2 bq = w2H[(nt*2 + kt)*32 + lane];
                mma16(c2[0][nt], afrag[0][kt], bq.x, bq.y);
                mma16(c2[1][nt], afrag[1][kt], bq.x, bq.y);
            }
        }

        // epilogue 1: relu(+b2), pack to fp16 A-frags (native layout match)
        uint af[2][4][4];
        #pragma unroll
        for (int kt = 0; kt < 4; ++kt) {
            const int colA = (2*kt)*8 + 2*tg;       // block 2kt   -> k 16kt+2tg
            const int colB = (2*kt+1)*8 + 2*tg;     // block 2kt+1 -> k 16kt+8+2tg
            const float bA0 = sb2[colA], bA1 = sb2[colA+1];
            const float bB0 = sb2[colB], bB1 = sb2[colB+1];
            #pragma unroll
            for (int mm = 0; mm < 2; ++mm) {
                af[mm][kt][0] = packh2(fmaxf(c2[mm][2*kt][0]   + bA0, 0.0f),
                                       fmaxf(c2[mm][2*kt][1]   + bA1, 0.0f));
                af[mm][kt][1] = packh2(fmaxf(c2[mm][2*kt][2]   + bA0, 0.0f),
                                       fmaxf(c2[mm][2*kt][3]   + bA1, 0.0f));
                af[mm][kt][2] = packh2(fmaxf(c2[mm][2*kt+1][0] + bB0, 0.0f),
                                       fmaxf(c2[mm][2*kt+1][1] + bB1, 0.0f));
                af[mm][kt][3] = packh2(fmaxf(c2[mm][2*kt+1][2] + bB0, 0.0f),
                                       fmaxf(c2[mm][2*kt+1][3] + bB1, 0.0f));
            }
        }

        // layer 3 (fp16 k16, 4 k-steps) + routed max-reduction epilogue
        const size_t rbA = ((size_t)(m*128 + pA)) * 128;
        const size_t rbB = ((size_t)(m*128 + pB)) * 128;
        #pragma unroll 1
        for (int pp = 0; pp < 2; ++pp) {
            #pragma unroll 1
            for (int nh = 0; nh < 2; ++nh) {
                float c3[2][4][4];
                #pragma unroll
                for (int n2 = 0; n2 < 4; ++n2)
                    #pragma unroll
                    for (int r = 0; r < 4; ++r) { c3[0][n2][r] = 0.0f; c3[1][n2][r] = 0.0f; }
                #pragma unroll
                for (int kt = 0; kt < 4; ++kt) {
                    #pragma unroll
                    for (int n2 = 0; n2 < 4; ++n2) {
                        const int ntg = pp*8 + nh*4 + n2;
                        uint2 bq = w3H[(ntg*4 + kt)*32 + lane];
                        mma16(c3[0][n2], af[0][kt], bq.x, bq.y);
                        mma16(c3[1][n2], af[1][kt], bq.x, bq.y);
                    }
                }
                #pragma unroll
                for (int mm = 0; mm < 2; ++mm) {
                    float P[4][2];
                    #pragma unroll
                    for (int n2 = 0; n2 < 4; ++n2) {
                        P[n2][0] = fmaxf(c3[mm][n2][0], c3[mm][n2][2]);
                        P[n2][1] = fmaxf(c3[mm][n2][1], c3[mm][n2][3]);
                    }
                    float e0 = g0 ? P[0][0] : P[1][0];
                    float e1 = g0 ? P[0][1] : P[1][1];
                    float e2 = g0 ? P[2][0] : P[3][0];
                    float e3 = g0 ? P[2][1] : P[3][1];
                    float K0v0 = g0 ? P[1][0] : P[0][0];
                    float K0v1 = g0 ? P[1][1] : P[0][1];
                    float K1v0 = g0 ? P[3][0] : P[2][0];
                    float K1v1 = g0 ? P[3][1] : P[2][1];
                    K0v0 = fmaxf(K0v0, __shfl_xor_sync(0xffffffffu, e0, 4));
                    K0v1 = fmaxf(K0v1, __shfl_xor_sync(0xffffffffu, e1, 4));
                    K1v0 = fmaxf(K1v0, __shfl_xor_sync(0xffffffffu, e2, 4));
                    K1v1 = fmaxf(K1v1, __shfl_xor_sync(0xffffffffu, e3, 4));
                    float f0  = g1 ? K0v0 : K1v0;
                    float f1  = g1 ? K0v1 : K1v1;
                    float Rv0 = g1 ? K1v0 : K0v0;
                    float Rv1 = g1 ? K1v1 : K0v1;
                    Rv0 = fmaxf(Rv0, __shfl_xor_sync(0xffffffffu, f0, 8));
                    Rv1 = fmaxf(Rv1, __shfl_xor_sync(0xffffffffu, f1, 8));
                    Rv0 = fmaxf(Rv0, __shfl_xor_sync(0xffffffffu, Rv0, 16));
                    Rv1 = fmaxf(Rv1, __shfl_xor_sync(0xffffffffu, Rv1, 16));
                    if (g2 == nh) {
                        const int col = (pp*8 + nh*4 + (g & 3))*8 + 2*tg;
                        float2 b3v = *(float2*)&sb3[col];
                        *(float2*)&out[(mm ? rbB : rbA) + col] =
                            make_float2(Rv0 + b3v.x, Rv1 + b3v.y);
                    }
                }
            }
        }
    }
}

extern "C" void kernel_launch(void* const* d_in, const int* in_sizes, int n_in,
                              void* d_out, int out_size)
{
    const float* windows = (const float*)d_in[0];
    const float* W1 = (const float*)d_in[1];
    const float* b1 = (const float*)d_in[2];
    const float* W2 = (const float*)d_in[3];
    const float* b2 = (const float*)d_in[4];
    const float* W3 = (const float*)d_in[5];
    const float* b3 = (const float*)d_in[6];
    float* out = (float*)d_out;

    cudaFuncSetAttribute(mini_embedding_mma,
                         cudaFuncAttributeMaxDynamicSharedMemorySize, SMEM_TOTAL);

    const int M = in_sizes[0] / (128 * 3);
    mini_embedding_mma<<<M, NT, SMEM_TOTAL>>>(windows, W1, b1, W2, b2, W3, b3, out);
}